// round 16
// baseline (speedup 1.0000x reference)
#include <cuda_runtime.h>
#include <cuda_fp16.h>
#include <stdint.h>

#define NN 50000
#define NE 800000
#define NG 256
#define INDIM 300
#define KP1 320          // x padded K (multiple of 64)
#define HID 256

// ---------------- scratch (device globals; no allocation allowed) ----------------
__device__ __align__(16) __half   g_x16[(size_t)NN * KP1];   // x in fp16, K padded
__device__ __align__(16) __half   g_t16[(size_t)NN * HID];   // transformed (h @ W), fp16
__device__ __align__(16) __half   g_a16[(size_t)NN * HID];   // aggregated output, fp16
// weights packed in lane-major B' layout (see k_cvt_w3 / load_tile)
__device__ __align__(16) uint32_t g_w1p[(KP1/2) * HID];
__device__ __align__(16) uint32_t g_w2p[(HID/2) * HID];
__device__ __align__(16) uint32_t g_w3p[(HID/2) * HID];
__device__ float g_dinv[NN];
__device__ int   g_cnt[NN];     // zero-init at load; re-zeroed by k_scan each run
__device__ int   g_rowptr[NN + 1];
__device__ int   g_cursor[NN];
__device__ int   g_csr_src[NE];
__device__ float g_csr_w[NE];

// ---------------- graph preprocessing ----------------
__global__ void k_hist(const int* __restrict__ ei) {
    int e = blockIdx.x * blockDim.x + threadIdx.x;
    if (e < NE) {
        int d = ei[NE + e];
        if (d >= 0 && d < NN) atomicAdd(&g_cnt[d], 1);
    }
}

__global__ void k_scan() {
    const int CH = (NN + 1023) / 1024;  // 49
    __shared__ int part[1024];
    int t = threadIdx.x;
    int begin = t * CH;
    int end = begin + CH; if (end > NN) end = NN; if (begin > NN) begin = NN;
    int s = 0;
    for (int i = begin; i < end; i++) s += g_cnt[i];
    part[t] = s;
    __syncthreads();
    if (t == 0) {
        int run = 0;
        for (int i = 0; i < 1024; i++) { int v = part[i]; part[i] = run; run += v; }
    }
    __syncthreads();
    int run = part[t];
    for (int i = begin; i < end; i++) {
        int c = g_cnt[i];
        g_rowptr[i] = run; run += c;
        g_dinv[i] = rsqrtf((float)(c + 1));
        g_cursor[i] = 0;
        g_cnt[i] = 0;
    }
    if (t == 1023) g_rowptr[NN] = run;
}

__global__ void k_build(const int* __restrict__ ei) {
    int e = blockIdx.x * blockDim.x + threadIdx.x;
    if (e >= NE) return;
    int s = ei[e];
    int d = ei[NE + e];
    if (s < 0 || s >= NN || d < 0 || d >= NN) return;
    int pos = g_rowptr[d] + atomicAdd(&g_cursor[d], 1);
    g_csr_src[pos] = s;
    g_csr_w[pos] = g_dinv[s] * g_dinv[d];
}

// ---------------- input conversions ----------------
__global__ void k_cvt_x(const float* __restrict__ x) {
    int i = blockIdx.x * blockDim.x + threadIdx.x;   // NN * 40
    if (i >= NN * (KP1 / 8)) return;
    int row = i / (KP1 / 8);
    int col = (i % (KP1 / 8)) * 8;
    uint4 o;
    __half2* oh = (__half2*)&o;
    if (col + 8 <= INDIM) {
        const float4* p = (const float4*)(x + (size_t)row * INDIM + col);
        float4 v0 = p[0], v1 = p[1];
        oh[0] = __floats2half2_rn(v0.x, v0.y);
        oh[1] = __floats2half2_rn(v0.z, v0.w);
        oh[2] = __floats2half2_rn(v1.x, v1.y);
        oh[3] = __floats2half2_rn(v1.z, v1.w);
    } else {
        float f[8];
        #pragma unroll
        for (int j = 0; j < 8; j++) {
            int c = col + j;
            f[j] = (c < INDIM) ? x[(size_t)row * INDIM + c] : 0.f;
        }
        oh[0] = __floats2half2_rn(f[0], f[1]);
        oh[1] = __floats2half2_rn(f[2], f[3]);
        oh[2] = __floats2half2_rn(f[4], f[5]);
        oh[3] = __floats2half2_rn(f[6], f[7]);
    }
    ((uint4*)g_x16)[i] = o;
}

// Pack weights in lane-major B' order:
//   value V(k2,n) = (half(W[2k2][n]), half(W[2k2+1][n]))
//   chunk = k2>>5, k2r = k2&31, kb8 = k2r>>3, tig = k2r&3, j = (k2r>>2)&1
//   nb = n>>7, wc = (n>>6)&1, nt = (n>>3)&7, gid = n&7
//   run  = (((chunk*2 + nb)*4 + kb8)*2 + wc)*32 + tig*8 + gid
//   gidx = run*16 + nt*2 + j
__global__ void k_cvt_w3(const float* __restrict__ W1,
                         const float* __restrict__ W2,
                         const float* __restrict__ W3) {
    const int N1 = (KP1 / 2) * HID;
    const int N2 = (HID / 2) * HID;
    int i = blockIdx.x * blockDim.x + threadIdx.x;
    const float* W; uint32_t* out; int K; int j;
    if (i < N1)                { W = W1; out = g_w1p; K = INDIM; j = i; }
    else if (i < N1 + N2)      { W = W2; out = g_w2p; K = HID;   j = i - N1; }
    else if (i < N1 + 2 * N2)  { W = W3; out = g_w3p; K = HID;   j = i - N1 - N2; }
    else return;
    int n = j % HID, k2 = j / HID;
    int ka = 2 * k2, kb = 2 * k2 + 1;
    float lo = (ka < K) ? W[(size_t)ka * HID + n] : 0.f;
    float hi = (kb < K) ? W[(size_t)kb * HID + n] : 0.f;
    __half2 h = __floats2half2_rn(lo, hi);

    int chunk = k2 >> 5, k2r = k2 & 31;
    int kb8 = k2r >> 3, tig = k2r & 3, jj = (k2r >> 2) & 1;
    int nb = n >> 7, wcx = (n >> 6) & 1, nt = (n >> 3) & 7, gid = n & 7;
    int run = (((chunk * 2 + nb) * 4 + kb8) * 2 + wcx) * 32 + tig * 8 + gid;
    out[run * 16 + nt * 2 + jj] = *(uint32_t*)&h;
}

// ---------------- fp16 mma.sync GEMM: ldmatrix A + lane-major B, BK=64 ----------------
__device__ __forceinline__ void cp16(uint32_t dst, const void* src, int srcbytes) {
    asm volatile("cp.async.cg.shared.global [%0], [%1], 16, %2;\n"
                 :: "r"(dst), "l"(src), "r"(srcbytes));
}
__device__ __forceinline__ void cp_commit() {
    asm volatile("cp.async.commit_group;\n");
}
__device__ __forceinline__ void cp_wait1() {
    asm volatile("cp.async.wait_group 1;\n");
}

// smem: A [2][128][72] halves (18432 B/buf), B' [2][256 runs][20 u32] (20480 B/buf)
#define A_STRIDE 72
#define A_BUF    9216          // halves per buffer
#define B_RUN    20            // u32 per run (16 used + pad)
#define B_BUFN   5120          // u32 per buffer (256 runs * 20)
#define SMEM_B_OFF 36864
#define GEMM_SMEM  (36864 + 40960)   // 77824 B

__global__ void __launch_bounds__(256) k_gemm_f16(int layer) {
    extern __shared__ char sm_raw[];
    __half* As = (__half*)sm_raw;
    uint32_t* Bs = (uint32_t*)(sm_raw + SMEM_B_OFF);

    const __half* A = (layer == 0) ? g_x16 : g_a16;
    const uint32_t* Bpk = (layer == 0) ? g_w1p : (layer == 1) ? g_w2p : g_w3p;
    const int K = (layer == 0) ? KP1 : HID;

    int bm = blockIdx.y * 128, bn = blockIdx.x * 128;
    int nb = bn >> 7;
    int tid = threadIdx.x;
    int wid = tid >> 5, lane = tid & 31;
    int wr = wid >> 1, wc = wid & 1;
    int gid = lane >> 2, tig = lane & 3;
    int lg = tig * 8 + gid;                  // B' lane-run index

    // ldmatrix per-lane source coords
    int mat = lane >> 3, r8 = lane & 7;
    int lm_row = wr * 32 + (mat & 1) * 8 + r8;   // + mt*16
    int lm_col = (mat >> 1) * 8;                 // + ks

    float acc[2][8][4];
    #pragma unroll
    for (int i = 0; i < 2; i++)
        #pragma unroll
        for (int j = 0; j < 8; j++)
            #pragma unroll
            for (int l = 0; l < 4; l++) acc[i][j][l] = 0.f;

    int T = K >> 6;

    auto load_tile = [&](int tile, int buf) {
        int k0 = tile << 6;
        // A: 128 rows x 64 halves = 1024 16B-chunks, 4/thread
        #pragma unroll
        for (int j = 0; j < 4; j++) {
            int idx = tid + 256 * j;
            int m = idx >> 3, kk = idx & 7;
            uint32_t dst = (uint32_t)__cvta_generic_to_shared(
                &As[buf * A_BUF + m * A_STRIDE + kk * 8]);
            int grow = bm + m;
            int bytes = (grow < NN) ? 16 : 0;
            const __half* src = bytes ? (A + (size_t)grow * K + k0 + kk * 8) : A;
            cp16(dst, src, bytes);
        }
        // B': 256 runs x 16 u32 = 1024 16B-chunks, 4/thread
        const uint32_t* gB = Bpk + (size_t)(tile * 2 + nb) * 4096;
        #pragma unroll
        for (int j = 0; j < 4; j++) {
            int idx = tid + 256 * j;
            int run = idx >> 2, w4 = (idx & 3) << 2;
            uint32_t dst = (uint32_t)__cvta_generic_to_shared(
                &Bs[buf * B_BUFN + run * B_RUN + w4]);
            cp16(dst, gB + run * 16 + w4, 16);
        }
    };

    load_tile(0, 0);
    cp_commit();

    for (int it = 0; it < T; it++) {
        if (it + 1 < T) load_tile(it + 1, (it + 1) & 1);
        cp_commit();
        cp_wait1();
        __syncthreads();

        int buf = it & 1;
        #pragma unroll
        for (int ks = 0; ks < 64; ks += 16) {
            int kb8 = ks >> 4;
            uint32_t a[2][4];
            #pragma unroll
            for (int mt = 0; mt < 2; mt++) {
                uint32_t saddr = (uint32_t)__cvta_generic_to_shared(
                    &As[buf * A_BUF + (lm_row + mt * 16) * A_STRIDE + ks + lm_col]);
                asm volatile(
                    "ldmatrix.sync.aligned.m8n8.x4.shared.b16 {%0,%1,%2,%3}, [%4];"
                    : "=r"(a[mt][0]), "=r"(a[mt][1]), "=r"(a[mt][2]), "=r"(a[mt][3])
                    : "r"(saddr));
            }
            const uint32_t* bb = &Bs[buf * B_BUFN + ((kb8 * 2 + wc) * 32 + lg) * B_RUN];
            uint4 v0 = *(const uint4*)&bb[0];
            uint4 v1 = *(const uint4*)&bb[4];
            uint4 v2 = *(const uint4*)&bb[8];
            uint4 v3 = *(const uint4*)&bb[12];
            uint32_t bv[16];
            *(uint4*)&bv[0] = v0; *(uint4*)&bv[4] = v1;
            *(uint4*)&bv[8] = v2; *(uint4*)&bv[12] = v3;
            #pragma unroll
            for (int mt = 0; mt < 2; mt++)
                #pragma unroll
                for (int nt = 0; nt < 8; nt++) {
                    asm volatile(
                        "mma.sync.aligned.m16n8k16.row.col.f32.f16.f16.f32 "
                        "{%0,%1,%2,%3}, {%4,%5,%6,%7}, {%8,%9}, {%0,%1,%2,%3};"
                        : "+f"(acc[mt][nt][0]), "+f"(acc[mt][nt][1]),
                          "+f"(acc[mt][nt][2]), "+f"(acc[mt][nt][3])
                        : "r"(a[mt][0]), "r"(a[mt][1]), "r"(a[mt][2]), "r"(a[mt][3]),
                          "r"(bv[nt * 2]), "r"(bv[nt * 2 + 1]));
                }
        }
        __syncthreads();
    }

    #pragma unroll
    for (int mt = 0; mt < 2; mt++) {
        #pragma unroll
        for (int nt = 0; nt < 8; nt++) {
            int r0 = bm + wr * 32 + mt * 16 + gid;
            int cc = bn + wc * 64 + nt * 8 + tig * 2;
            if (r0 < NN) {
                __half2 h = __floats2half2_rn(acc[mt][nt][0], acc[mt][nt][1]);
                *(__half2*)(g_t16 + (size_t)r0 * 256 + cc) = h;
            }
            if (r0 + 8 < NN) {
                __half2 h = __floats2half2_rn(acc[mt][nt][2], acc[mt][nt][3]);
                *(__half2*)(g_t16 + (size_t)(r0 + 8) * 256 + cc) = h;
            }
        }
    }
}

// ---------------- aggregation: 1 warp/node, fp16 gather + fp16 writeback ----------------
__device__ __forceinline__ void acc8(float* a, uint4 v, float w) {
    __half2* h = (__half2*)&v;
    #pragma unroll
    for (int j = 0; j < 4; j++) {
        float2 f = __half22float2(h[j]);
        a[2 * j + 0] += w * f.x;
        a[2 * j + 1] += w * f.y;
    }
}

__global__ void k_agg(const float* __restrict__ bias, int relu) {
    int gw = (blockIdx.x * blockDim.x + threadIdx.x) >> 5;
    int lane = threadIdx.x & 31;
    if (gw >= NN) return;
    int n = gw;
    const uint4* t4 = (const uint4*)g_t16;

    float dn = g_dinv[n];
    float sw = dn * dn;
    float a[8] = {};
    acc8(a, __ldg(&t4[(size_t)n * 32 + lane]), sw);

    int beg = g_rowptr[n], end = g_rowptr[n + 1];
    int i = beg;
    for (; i + 4 <= end; i += 4) {
        int s0 = g_csr_src[i],   s1 = g_csr_src[i+1];
        int s2 = g_csr_src[i+2], s3 = g_csr_src[i+3];
        float w0 = g_csr_w[i],   w1 = g_csr_w[i+1];
        float w2 = g_csr_w[i+2], w3 = g_csr_w[i+3];
        uint4 v0 = __ldg(&t4[(size_t)s0 * 32 + lane]);
        uint4 v1 = __ldg(&t4[(size_t)s1 * 32 + lane]);
        uint4 v2 = __ldg(&t4[(size_t)s2 * 32 + lane]);
        uint4 v3 = __ldg(&t4[(size_t)s3 * 32 + lane]);
        acc8(a, v0, w0); acc8(a, v1, w1); acc8(a, v2, w2); acc8(a, v3, w3);
    }
    for (; i < end; i++) {
        int s = g_csr_src[i];
        float w = g_csr_w[i];
        acc8(a, __ldg(&t4[(size_t)s * 32 + lane]), w);
    }

    float4 b0 = ((const float4*)bias)[lane * 2];
    float4 b1 = ((const float4*)bias)[lane * 2 + 1];
    a[0] += b0.x; a[1] += b0.y; a[2] += b0.z; a[3] += b0.w;
    a[4] += b1.x; a[5] += b1.y; a[6] += b1.z; a[7] += b1.w;
    if (relu) {
        #pragma unroll
        for (int j = 0; j < 8; j++) a[j] = fmaxf(a[j], 0.f);
    }
    uint4 o;
    __half2* oh = (__half2*)&o;
    oh[0] = __floats2half2_rn(a[0], a[1]);
    oh[1] = __floats2half2_rn(a[2], a[3]);
    oh[2] = __floats2half2_rn(a[4], a[5]);
    oh[3] = __floats2half2_rn(a[6], a[7]);
    ((uint4*)g_a16)[(size_t)n * 32 + lane] = o;
}

// ---------------- fused mean-pool + classifier ----------------
__global__ void k_head(const int* __restrict__ batch,
                       const float* __restrict__ Wc1, const float* __restrict__ bc1,
                       const float* __restrict__ Wc2, const float* __restrict__ bc2,
                       const float* __restrict__ Wc3, const float* __restrict__ bc3,
                       float* __restrict__ out) {
    int g = blockIdx.x, t = threadIdx.x;
    __shared__ float p[256], q1[16], q2[64];
    __shared__ int slo, shi;
    if (t == 0) {
        int l = 0, r = NN;
        while (l < r) { int m = (l + r) >> 1; if (batch[m] < g) l = m + 1; else r = m; }
        slo = l;
        l = 0; r = NN;
        while (l < r) { int m = (l + r) >> 1; if (batch[m] < g + 1) l = m + 1; else r = m; }
        shi = l;
    }
    __syncthreads();
    int lo = slo, hi = shi;
    float s = 0.f;
    for (int n = lo; n < hi; n++) s += __half2float(g_a16[(size_t)n * 256 + t]);
    int cnt = hi - lo;
    float inv = (cnt > 0) ? (1.0f / (float)cnt) : 1.0f;
    p[t] = s * inv;
    __syncthreads();

    float* o1 = out;
    float* o2 = out + 256 * 16;
    float* o3 = out + 256 * 16 + 256 * 64;

    if (t < 16) {
        float v = bc1[t];
        for (int k = 0; k < 256; k++) v += p[k] * Wc1[k * 16 + t];
        q1[t] = v;
        o1[g * 16 + t] = v;
    }
    __syncthreads();
    if (t == 0) {
        float m = q1[0];
        for (int i = 1; i < 16; i++) m = fmaxf(m, q1[i]);
        float sum = 0.f;
        for (int i = 0; i < 16; i++) { q1[i] = expf(q1[i] - m); sum += q1[i]; }
        float inv2 = 1.f / sum;
        for (int i = 0; i < 16; i++) q1[i] *= inv2;
    }
    __syncthreads();
    if (t < 64) {
        float v = bc2[t];
        for (int k = 0; k < 256; k++) v += p[k] * Wc2[k * 64 + t];
        for (int k = 0; k < 16; k++) v += q1[k] * Wc2[(256 + k) * 64 + t];
        q2[t] = v;
        o2[g * 64 + t] = v;
    }
    __syncthreads();
    if (t == 0) {
        float m = q2[0];
        for (int i = 1; i < 64; i++) m = fmaxf(m, q2[i]);
        float sum = 0.f;
        for (int i = 0; i < 64; i++) { q2[i] = expf(q2[i] - m); sum += q2[i]; }
        float inv2 = 1.f / sum;
        for (int i = 0; i < 64; i++) q2[i] *= inv2;
    }
    __syncthreads();
    {
        float v = bc3[t];
        for (int k = 0; k < 256; k++) v += p[k] * Wc3[k * 256 + t];
        for (int k = 0; k < 64; k++) v += q2[k] * Wc3[(256 + k) * 256 + t];
        o3[g * 256 + t] = v;
    }
}

// ---------------- launch: fork CSR || cvt+gemm1 (gemm1 at launch index 3 for ncu) ----------------
extern "C" void kernel_launch(void* const* d_in, const int* in_sizes, int n_in,
                              void* d_out, int out_size) {
    const float* x     = (const float*)d_in[0];
    const int*   ei    = (const int*)d_in[1];
    const int*   batch = (const int*)d_in[2];
    const float* W1 = (const float*)d_in[3],  *b1 = (const float*)d_in[4];
    const float* W2 = (const float*)d_in[5],  *b2 = (const float*)d_in[6];
    const float* W3 = (const float*)d_in[7],  *b3 = (const float*)d_in[8];
    const float* Wc1 = (const float*)d_in[9],  *bc1 = (const float*)d_in[10];
    const float* Wc2 = (const float*)d_in[11], *bc2 = (const float*)d_in[12];
    const float* Wc3 = (const float*)d_in[13], *bc3 = (const float*)d_in[14];
    float* out = (float*)d_out;

    static cudaStream_t s2 = nullptr;
    static cudaEvent_t evf = nullptr, evj = nullptr;
    if (s2 == nullptr) {
        cudaStreamCreateWithFlags(&s2, cudaStreamNonBlocking);
        cudaEventCreateWithFlags(&evf, cudaEventDisableTiming);
        cudaEventCreateWithFlags(&evj, cudaEventDisableTiming);
        cudaFuncSetAttribute(k_gemm_f16, cudaFuncAttributeMaxDynamicSharedMemorySize, GEMM_SMEM);
    }

    dim3 gg(2, (NN + 127) / 128);  // (2, 391)
    int agg_blocks = (NN * 32 + 255) / 256;
    const int NW = (KP1 / 2) * HID + 2 * (HID / 2) * HID;
    const int NX8 = NN * (KP1 / 8);

    // fork (issue order keeps k_gemm_f16 at launch index 3 for ncu)
    cudaEventRecord(evf, 0);
    cudaStreamWaitEvent(s2, evf, 0);

    k_hist<<<NE / 256, 256>>>(ei);                                 // idx 0
    k_cvt_x<<<(NX8 + 255) / 256, 256, 0, s2>>>(x);                 // idx 1
    k_cvt_w3<<<(NW + 255) / 256, 256, 0, s2>>>(W1, W2, W3);        // idx 2
    k_gemm_f16<<<gg, 256, GEMM_SMEM, s2>>>(0);                     // idx 3
    k_scan<<<1, 1024>>>();                                         // idx 4
    k_build<<<NE / 256, 256>>>(ei);                                // idx 5

    // join
    cudaEventRecord(evj, s2);
    cudaStreamWaitEvent(0, evj, 0);

    // serial layers
    k_agg<<<agg_blocks, 256>>>(b1, 1);
    k_gemm_f16<<<gg, 256, GEMM_SMEM>>>(1);
    k_agg<<<agg_blocks, 256>>>(b2, 1);
    k_gemm_f16<<<gg, 256, GEMM_SMEM>>>(2);
    k_agg<<<agg_blocks, 256>>>(b3, 0);

    k_head<<<NG, 256>>>(batch, Wc1, bc1, Wc2, bc2, Wc3, bc3, out);
}

// round 17
// speedup vs baseline: 1.0879x; 1.0879x over previous
#include <cuda_runtime.h>
#include <cuda_fp16.h>
#include <stdint.h>

#define NN 50000
#define NE 800000
#define NG 256
#define INDIM 300
#define KP1 320          // x padded K (multiple of 64)
#define HID 256

// ---------------- scratch (device globals; no allocation allowed) ----------------
__device__ __align__(16) __half   g_x16[(size_t)NN * KP1];   // x in fp16, K padded
__device__ __align__(16) __half   g_t16[(size_t)NN * HID];   // transformed (h @ W), fp16
__device__ __align__(16) __half   g_a16[(size_t)NN * HID];   // aggregated output, fp16
__device__ __align__(16) uint32_t g_w1p[(KP1/2) * HID];      // W packed k-pairs (fp16x2)
__device__ __align__(16) uint32_t g_w2p[(HID/2) * HID];
__device__ __align__(16) uint32_t g_w3p[(HID/2) * HID];
__device__ float g_dinv[NN];
__device__ int   g_cnt[NN];     // zero-init at load; re-zeroed by k_scan each run
__device__ int   g_rowptr[NN + 1];
__device__ int   g_cursor[NN];
__device__ int   g_csr_src[NE];
__device__ float g_csr_w[NE];

// ---------------- graph preprocessing ----------------
__global__ void k_hist(const int* __restrict__ ei) {
    int e = blockIdx.x * blockDim.x + threadIdx.x;
    if (e < NE) {
        int d = ei[NE + e];
        if (d >= 0 && d < NN) atomicAdd(&g_cnt[d], 1);
    }
}

__global__ void k_scan() {
    const int CH = (NN + 1023) / 1024;  // 49
    __shared__ int part[1024];
    int t = threadIdx.x;
    int begin = t * CH;
    int end = begin + CH; if (end > NN) end = NN; if (begin > NN) begin = NN;
    int s = 0;
    for (int i = begin; i < end; i++) s += g_cnt[i];
    part[t] = s;
    __syncthreads();
    if (t == 0) {
        int run = 0;
        for (int i = 0; i < 1024; i++) { int v = part[i]; part[i] = run; run += v; }
    }
    __syncthreads();
    int run = part[t];
    for (int i = begin; i < end; i++) {
        int c = g_cnt[i];
        g_rowptr[i] = run; run += c;
        g_dinv[i] = rsqrtf((float)(c + 1));
        g_cursor[i] = 0;
        g_cnt[i] = 0;
    }
    if (t == 1023) g_rowptr[NN] = run;
}

__global__ void k_build(const int* __restrict__ ei) {
    int e = blockIdx.x * blockDim.x + threadIdx.x;
    if (e >= NE) return;
    int s = ei[e];
    int d = ei[NE + e];
    if (s < 0 || s >= NN || d < 0 || d >= NN) return;
    int pos = g_rowptr[d] + atomicAdd(&g_cursor[d], 1);
    g_csr_src[pos] = s;
    g_csr_w[pos] = g_dinv[s] * g_dinv[d];
}

// ---------------- input conversions ----------------
__global__ void k_cvt_x(const float* __restrict__ x) {
    int i = blockIdx.x * blockDim.x + threadIdx.x;   // NN * 40
    if (i >= NN * (KP1 / 8)) return;
    int row = i / (KP1 / 8);
    int col = (i % (KP1 / 8)) * 8;
    uint4 o;
    __half2* oh = (__half2*)&o;
    if (col + 8 <= INDIM) {
        const float4* p = (const float4*)(x + (size_t)row * INDIM + col);
        float4 v0 = p[0], v1 = p[1];
        oh[0] = __floats2half2_rn(v0.x, v0.y);
        oh[1] = __floats2half2_rn(v0.z, v0.w);
        oh[2] = __floats2half2_rn(v1.x, v1.y);
        oh[3] = __floats2half2_rn(v1.z, v1.w);
    } else {
        float f[8];
        #pragma unroll
        for (int j = 0; j < 8; j++) {
            int c = col + j;
            f[j] = (c < INDIM) ? x[(size_t)row * INDIM + c] : 0.f;
        }
        oh[0] = __floats2half2_rn(f[0], f[1]);
        oh[1] = __floats2half2_rn(f[2], f[3]);
        oh[2] = __floats2half2_rn(f[4], f[5]);
        oh[3] = __floats2half2_rn(f[6], f[7]);
    }
    ((uint4*)g_x16)[i] = o;
}

// pack W[K][256] fp32 -> out[k2][n] = (half(W[2k2][n]), half(W[2k2+1][n]))
__global__ void k_cvt_w3(const float* __restrict__ W1,
                         const float* __restrict__ W2,
                         const float* __restrict__ W3) {
    const int N1 = (KP1 / 2) * HID;
    const int N2 = (HID / 2) * HID;
    int i = blockIdx.x * blockDim.x + threadIdx.x;
    const float* W; uint32_t* out; int K; int j;
    if (i < N1)                { W = W1; out = g_w1p; K = INDIM; j = i; }
    else if (i < N1 + N2)      { W = W2; out = g_w2p; K = HID;   j = i - N1; }
    else if (i < N1 + 2 * N2)  { W = W3; out = g_w3p; K = HID;   j = i - N1 - N2; }
    else return;
    int n = j % HID, k2 = j / HID;
    int ka = 2 * k2, kb = 2 * k2 + 1;
    float lo = (ka < K) ? W[(size_t)ka * HID + n] : 0.f;
    float hi = (kb < K) ? W[(size_t)kb * HID + n] : 0.f;
    __half2 h = __floats2half2_rn(lo, hi);
    out[j] = *(uint32_t*)&h;
}

// ---------------- fp16 mma.sync GEMM: ldmatrix A + R15 B path, BK=64 ----------------
__device__ __forceinline__ void cp16(uint32_t dst, const void* src, int srcbytes) {
    asm volatile("cp.async.cg.shared.global [%0], [%1], 16, %2;\n"
                 :: "r"(dst), "l"(src), "r"(srcbytes));
}
__device__ __forceinline__ void cp_commit() {
    asm volatile("cp.async.commit_group;\n");
}
__device__ __forceinline__ void cp_wait1() {
    asm volatile("cp.async.wait_group 1;\n");
}

// smem: A [2][128][72] halves (18432 B/buf), B [2][32][136] u32 (17408 B/buf)
#define A_STRIDE 72
#define A_BUF    9216
#define B_STRIDE 136
#define B_BUF    4352
#define SMEM_B_OFF 36864
#define GEMM_SMEM  (36864 + 34816)   // 71680 B

__global__ void __launch_bounds__(256) k_gemm_f16(int layer) {
    extern __shared__ char sm_raw[];
    __half* As = (__half*)sm_raw;
    uint32_t* Bs = (uint32_t*)(sm_raw + SMEM_B_OFF);

    const __half* A = (layer == 0) ? g_x16 : g_a16;
    const uint32_t* Bpk = (layer == 0) ? g_w1p : (layer == 1) ? g_w2p : g_w3p;
    const int K = (layer == 0) ? KP1 : HID;

    int bm = blockIdx.y * 128, bn = blockIdx.x * 128;
    int tid = threadIdx.x;
    int wid = tid >> 5, lane = tid & 31;
    int wr = wid >> 1, wc = wid & 1;
    int gid = lane >> 2, tig = lane & 3;

    // ldmatrix per-lane source coords (verified mapping from R16)
    int mat = lane >> 3, r8 = lane & 7;
    int lm_row = wr * 32 + (mat & 1) * 8 + r8;   // + mt*16
    int lm_col = (mat >> 1) * 8;                 // + ks

    float acc[2][8][4];
    #pragma unroll
    for (int i = 0; i < 2; i++)
        #pragma unroll
        for (int j = 0; j < 8; j++)
            #pragma unroll
            for (int l = 0; l < 4; l++) acc[i][j][l] = 0.f;

    int T = K >> 6;   // K multiple of 64

    auto load_tile = [&](int tile, int buf) {
        int k0 = tile << 6;
        // A: 128 rows x 64 halves = 1024 16B-chunks, 4/thread
        #pragma unroll
        for (int j = 0; j < 4; j++) {
            int idx = tid + 256 * j;
            int m = idx >> 3, kk = idx & 7;
            uint32_t dst = (uint32_t)__cvta_generic_to_shared(
                &As[buf * A_BUF + m * A_STRIDE + kk * 8]);
            int grow = bm + m;
            int bytes = (grow < NN) ? 16 : 0;
            const __half* src = bytes ? (A + (size_t)grow * K + k0 + kk * 8) : A;
            cp16(dst, src, bytes);
        }
        // B: 32 k2-rows x 128 u32 = 1024 16B-chunks, 4/thread
        int k20 = k0 >> 1;
        #pragma unroll
        for (int j = 0; j < 4; j++) {
            int idx = tid + 256 * j;
            int r = idx >> 5, c4 = (idx & 31) << 2;
            uint32_t dst = (uint32_t)__cvta_generic_to_shared(
                &Bs[buf * B_BUF + r * B_STRIDE + c4]);
            cp16(dst, Bpk + (size_t)(k20 + r) * 256 + bn + c4, 16);
        }
    };

    load_tile(0, 0);
    cp_commit();

    for (int it = 0; it < T; it++) {
        if (it + 1 < T) load_tile(it + 1, (it + 1) & 1);
        cp_commit();
        cp_wait1();
        __syncthreads();

        int buf = it & 1;
        #pragma unroll
        for (int ks = 0; ks < 64; ks += 16) {
            uint32_t a[2][4], b[8][2];
            #pragma unroll
            for (int mt = 0; mt < 2; mt++) {
                uint32_t saddr = (uint32_t)__cvta_generic_to_shared(
                    &As[buf * A_BUF + (lm_row + mt * 16) * A_STRIDE + ks + lm_col]);
                asm volatile(
                    "ldmatrix.sync.aligned.m8n8.x4.shared.b16 {%0,%1,%2,%3}, [%4];"
                    : "=r"(a[mt][0]), "=r"(a[mt][1]), "=r"(a[mt][2]), "=r"(a[mt][3])
                    : "r"(saddr));
            }
            int kb = ks >> 1;
            #pragma unroll
            for (int nt = 0; nt < 8; nt++) {
                int c = wc * 64 + nt * 8 + gid;
                const uint32_t* bb = &Bs[buf * B_BUF];
                b[nt][0] = bb[(kb + tig) * B_STRIDE + c];
                b[nt][1] = bb[(kb + tig + 4) * B_STRIDE + c];
            }
            #pragma unroll
            for (int mt = 0; mt < 2; mt++)
                #pragma unroll
                for (int nt = 0; nt < 8; nt++) {
                    asm volatile(
                        "mma.sync.aligned.m16n8k16.row.col.f32.f16.f16.f32 "
                        "{%0,%1,%2,%3}, {%4,%5,%6,%7}, {%8,%9}, {%0,%1,%2,%3};"
                        : "+f"(acc[mt][nt][0]), "+f"(acc[mt][nt][1]),
                          "+f"(acc[mt][nt][2]), "+f"(acc[mt][nt][3])
                        : "r"(a[mt][0]), "r"(a[mt][1]), "r"(a[mt][2]), "r"(a[mt][3]),
                          "r"(b[nt][0]), "r"(b[nt][1]));
                }
        }
        __syncthreads();
    }

    #pragma unroll
    for (int mt = 0; mt < 2; mt++) {
        #pragma unroll
        for (int nt = 0; nt < 8; nt++) {
            int r0 = bm + wr * 32 + mt * 16 + gid;
            int cc = bn + wc * 64 + nt * 8 + tig * 2;
            if (r0 < NN) {
                __half2 h = __floats2half2_rn(acc[mt][nt][0], acc[mt][nt][1]);
                *(__half2*)(g_t16 + (size_t)r0 * 256 + cc) = h;
            }
            if (r0 + 8 < NN) {
                __half2 h = __floats2half2_rn(acc[mt][nt][2], acc[mt][nt][3]);
                *(__half2*)(g_t16 + (size_t)(r0 + 8) * 256 + cc) = h;
            }
        }
    }
}

// ---------------- aggregation: 1 warp/node, fp16 gather + fp16 writeback ----------------
__device__ __forceinline__ void acc8(float* a, uint4 v, float w) {
    __half2* h = (__half2*)&v;
    #pragma unroll
    for (int j = 0; j < 4; j++) {
        float2 f = __half22float2(h[j]);
        a[2 * j + 0] += w * f.x;
        a[2 * j + 1] += w * f.y;
    }
}

__global__ void k_agg(const float* __restrict__ bias, int relu) {
    int gw = (blockIdx.x * blockDim.x + threadIdx.x) >> 5;
    int lane = threadIdx.x & 31;
    if (gw >= NN) return;
    int n = gw;
    const uint4* t4 = (const uint4*)g_t16;

    float dn = g_dinv[n];
    float sw = dn * dn;
    float a[8] = {};
    acc8(a, __ldg(&t4[(size_t)n * 32 + lane]), sw);

    int beg = g_rowptr[n], end = g_rowptr[n + 1];
    int i = beg;
    for (; i + 4 <= end; i += 4) {
        int s0 = g_csr_src[i],   s1 = g_csr_src[i+1];
        int s2 = g_csr_src[i+2], s3 = g_csr_src[i+3];
        float w0 = g_csr_w[i],   w1 = g_csr_w[i+1];
        float w2 = g_csr_w[i+2], w3 = g_csr_w[i+3];
        uint4 v0 = __ldg(&t4[(size_t)s0 * 32 + lane]);
        uint4 v1 = __ldg(&t4[(size_t)s1 * 32 + lane]);
        uint4 v2 = __ldg(&t4[(size_t)s2 * 32 + lane]);
        uint4 v3 = __ldg(&t4[(size_t)s3 * 32 + lane]);
        acc8(a, v0, w0); acc8(a, v1, w1); acc8(a, v2, w2); acc8(a, v3, w3);
    }
    for (; i < end; i++) {
        int s = g_csr_src[i];
        float w = g_csr_w[i];
        acc8(a, __ldg(&t4[(size_t)s * 32 + lane]), w);
    }

    float4 b0 = ((const float4*)bias)[lane * 2];
    float4 b1 = ((const float4*)bias)[lane * 2 + 1];
    a[0] += b0.x; a[1] += b0.y; a[2] += b0.z; a[3] += b0.w;
    a[4] += b1.x; a[5] += b1.y; a[6] += b1.z; a[7] += b1.w;
    if (relu) {
        #pragma unroll
        for (int j = 0; j < 8; j++) a[j] = fmaxf(a[j], 0.f);
    }
    uint4 o;
    __half2* oh = (__half2*)&o;
    oh[0] = __floats2half2_rn(a[0], a[1]);
    oh[1] = __floats2half2_rn(a[2], a[3]);
    oh[2] = __floats2half2_rn(a[4], a[5]);
    oh[3] = __floats2half2_rn(a[6], a[7]);
    ((uint4*)g_a16)[(size_t)n * 32 + lane] = o;
}

// ---------------- fused mean-pool + classifier ----------------
__global__ void k_head(const int* __restrict__ batch,
                       const float* __restrict__ Wc1, const float* __restrict__ bc1,
                       const float* __restrict__ Wc2, const float* __restrict__ bc2,
                       const float* __restrict__ Wc3, const float* __restrict__ bc3,
                       float* __restrict__ out) {
    int g = blockIdx.x, t = threadIdx.x;
    __shared__ float p[256], q1[16], q2[64];
    __shared__ int slo, shi;
    if (t == 0) {
        int l = 0, r = NN;
        while (l < r) { int m = (l + r) >> 1; if (batch[m] < g) l = m + 1; else r = m; }
        slo = l;
        l = 0; r = NN;
        while (l < r) { int m = (l + r) >> 1; if (batch[m] < g + 1) l = m + 1; else r = m; }
        shi = l;
    }
    __syncthreads();
    int lo = slo, hi = shi;
    float s = 0.f;
    for (int n = lo; n < hi; n++) s += __half2float(g_a16[(size_t)n * 256 + t]);
    int cnt = hi - lo;
    float inv = (cnt > 0) ? (1.0f / (float)cnt) : 1.0f;
    p[t] = s * inv;
    __syncthreads();

    float* o1 = out;
    float* o2 = out + 256 * 16;
    float* o3 = out + 256 * 16 + 256 * 64;

    if (t < 16) {
        float v = bc1[t];
        for (int k = 0; k < 256; k++) v += p[k] * Wc1[k * 16 + t];
        q1[t] = v;
        o1[g * 16 + t] = v;
    }
    __syncthreads();
    if (t == 0) {
        float m = q1[0];
        for (int i = 1; i < 16; i++) m = fmaxf(m, q1[i]);
        float sum = 0.f;
        for (int i = 0; i < 16; i++) { q1[i] = expf(q1[i] - m); sum += q1[i]; }
        float inv2 = 1.f / sum;
        for (int i = 0; i < 16; i++) q1[i] *= inv2;
    }
    __syncthreads();
    if (t < 64) {
        float v = bc2[t];
        for (int k = 0; k < 256; k++) v += p[k] * Wc2[k * 64 + t];
        for (int k = 0; k < 16; k++) v += q1[k] * Wc2[(256 + k) * 64 + t];
        q2[t] = v;
        o2[g * 64 + t] = v;
    }
    __syncthreads();
    if (t == 0) {
        float m = q2[0];
        for (int i = 1; i < 64; i++) m = fmaxf(m, q2[i]);
        float sum = 0.f;
        for (int i = 0; i < 64; i++) { q2[i] = expf(q2[i] - m); sum += q2[i]; }
        float inv2 = 1.f / sum;
        for (int i = 0; i < 64; i++) q2[i] *= inv2;
    }
    __syncthreads();
    {
        float v = bc3[t];
        for (int k = 0; k < 256; k++) v += p[k] * Wc3[k * 256 + t];
        for (int k = 0; k < 64; k++) v += q2[k] * Wc3[(256 + k) * 256 + t];
        o3[g * 256 + t] = v;
    }
}

// ---------------- launch: fork CSR || cvt+gemm1 (gemm1 at launch index 3 for ncu) ----------------
extern "C" void kernel_launch(void* const* d_in, const int* in_sizes, int n_in,
                              void* d_out, int out_size) {
    const float* x     = (const float*)d_in[0];
    const int*   ei    = (const int*)d_in[1];
    const int*   batch = (const int*)d_in[2];
    const float* W1 = (const float*)d_in[3],  *b1 = (const float*)d_in[4];
    const float* W2 = (const float*)d_in[5],  *b2 = (const float*)d_in[6];
    const float* W3 = (const float*)d_in[7],  *b3 = (const float*)d_in[8];
    const float* Wc1 = (const float*)d_in[9],  *bc1 = (const float*)d_in[10];
    const float* Wc2 = (const float*)d_in[11], *bc2 = (const float*)d_in[12];
    const float* Wc3 = (const float*)d_in[13], *bc3 = (const float*)d_in[14];
    float* out = (float*)d_out;

    static cudaStream_t s2 = nullptr;
    static cudaEvent_t evf = nullptr, evj = nullptr;
    if (s2 == nullptr) {
        cudaStreamCreateWithFlags(&s2, cudaStreamNonBlocking);
        cudaEventCreateWithFlags(&evf, cudaEventDisableTiming);
        cudaEventCreateWithFlags(&evj, cudaEventDisableTiming);
        cudaFuncSetAttribute(k_gemm_f16, cudaFuncAttributeMaxDynamicSharedMemorySize, GEMM_SMEM);
    }

    dim3 gg(2, (NN + 127) / 128);  // (2, 391)
    int agg_blocks = (NN * 32 + 255) / 256;
    const int NW = (KP1 / 2) * HID + 2 * (HID / 2) * HID;
    const int NX8 = NN * (KP1 / 8);

    // fork (issue order keeps k_gemm_f16 at launch index 3 for ncu)
    cudaEventRecord(evf, 0);
    cudaStreamWaitEvent(s2, evf, 0);

    k_hist<<<NE / 256, 256>>>(ei);                                 // idx 0
    k_cvt_x<<<(NX8 + 255) / 256, 256, 0, s2>>>(x);                 // idx 1
    k_cvt_w3<<<(NW + 255) / 256, 256, 0, s2>>>(W1, W2, W3);        // idx 2
    k_gemm_f16<<<gg, 256, GEMM_SMEM, s2>>>(0);                     // idx 3
    k_scan<<<1, 1024>>>();                                         // idx 4
    k_build<<<NE / 256, 256>>>(ei);                                // idx 5

    // join
    cudaEventRecord(evj, s2);
    cudaStreamWaitEvent(0, evj, 0);

    // serial layers
    k_agg<<<agg_blocks, 256>>>(b1, 1);
    k_gemm_f16<<<gg, 256, GEMM_SMEM>>>(1);
    k_agg<<<agg_blocks, 256>>>(b2, 1);
    k_gemm_f16<<<gg, 256, GEMM_SMEM>>>(2);
    k_agg<<<agg_blocks, 256>>>(b3, 0);

    k_head<<<NG, 256>>>(batch, Wc1, bc1, Wc2, bc2, Wc3, bc3, out);
}